// round 1
// baseline (speedup 1.0000x reference)
#include <cuda_runtime.h>
#include <cuda_bf16.h>
#include <math.h>
#include <float.h>

// Problem constants
#define NPTS   131072          // 32 * 64 * 64 points
#define DDIM   64
#define KCODES 1024
#define HWSZ   4096            // 64*64
#define QOFF   ((size_t)NPTS)  // quantized segment offset in out
#define QSZ    ((size_t)32*64*4096)
#define POFF   (QOFF + QSZ)    // perplexity scalar offset

// Scratch (no cudaMalloc allowed)
__device__ int   g_counts[KCODES];
__device__ float g_esq[KCODES];

// ---------------------------------------------------------------------------
// Prep: ||e_k||^2 per code, zero histogram. 1024 threads.
// ---------------------------------------------------------------------------
__global__ void vq_prep(const float* __restrict__ emb) {
    int k = blockIdx.x * blockDim.x + threadIdx.x;
    if (k < KCODES) {
        const float4* row = (const float4*)(emb + (size_t)k * DDIM);
        float s = 0.f;
#pragma unroll
        for (int i = 0; i < DDIM / 4; i++) {
            float4 v = row[i];
            s += v.x * v.x + v.y * v.y + v.z * v.z + v.w * v.w;
        }
        g_esq[k]    = s;
        g_counts[k] = 0;
    }
}

// ---------------------------------------------------------------------------
// Main: per-point argmin over 1024 codes + gather + index write + histogram.
// in:  (B=32, C=64, H=64, W=64) fp32
// out: [idx(131072) | quantized(B,C,H,W) | perplexity]
// ---------------------------------------------------------------------------
#define CHUNK 128   // codes per smem tile (128*64*4B = 32KB)

__global__ __launch_bounds__(256)
void vq_main(const float* __restrict__ in, const float* __restrict__ emb,
             float* __restrict__ out) {
    __shared__ float se[CHUNK * DDIM];   // 32 KB
    __shared__ float ssq[CHUNK];

    const int n  = blockIdx.x * 256 + threadIdx.x;   // point id
    const int b  = n >> 12;                          // 4096 pts per image
    const int hw = n & (HWSZ - 1);
    const float* xb = in + (size_t)b * DDIM * HWSZ + hw;

    // Load x (stride-4096 per dim; coalesced across warp) into 32 packed pairs
    unsigned long long xr[DDIM / 2];
#pragma unroll
    for (int d = 0; d < DDIM / 2; d++) {
        float a = xb[(size_t)(2 * d)     * HWSZ];
        float c = xb[(size_t)(2 * d + 1) * HWSZ];
        asm("mov.b64 %0, {%1, %2};" : "=l"(xr[d]) : "f"(a), "f"(c));
    }

    float best = FLT_MAX;
    int   bidx = 0;

    for (int c0 = 0; c0 < KCODES; c0 += CHUNK) {
        __syncthreads();
        // cooperative tile load: CHUNK*64 floats = 2048 float4, 8 per thread
        {
            const float4* src = (const float4*)(emb + (size_t)c0 * DDIM);
            float4* dst = (float4*)se;
#pragma unroll
            for (int i = 0; i < (CHUNK * DDIM / 4) / 256; i++)
                dst[threadIdx.x + i * 256] = src[threadIdx.x + i * 256];
            if (threadIdx.x < CHUNK)
                ssq[threadIdx.x] = g_esq[c0 + threadIdx.x];
        }
        __syncthreads();

#pragma unroll 4
        for (int kk = 0; kk < CHUNK; kk++) {
            const unsigned long long* e2 =
                (const unsigned long long*)(se + kk * DDIM);
            unsigned long long acc = 0ull;   // packed (0.0f, 0.0f)
#pragma unroll
            for (int d = 0; d < DDIM / 2; d++) {
                unsigned long long ev = e2[d];   // warp-broadcast LDS
                asm("fma.rn.f32x2 %0, %1, %2, %0;"
                    : "+l"(acc) : "l"(xr[d]), "l"(ev));
            }
            float lo = __uint_as_float((unsigned int)acc);
            float hi = __uint_as_float((unsigned int)(acc >> 32));
            float dot  = lo + hi;
            float dist = ssq[kk] - 2.0f * dot;   // ||x||^2 dropped (row-const)
            if (dist < best) { best = dist; bidx = c0 + kk; }
        }
    }

    // ---- epilogue ----
    out[n] = (float)bidx;                    // indices (as fp32)
    atomicAdd(&g_counts[bidx], 1);           // usage histogram

    // quantized = e[bidx], written transposed to (B, C, H, W)
    const float4* er = (const float4*)(emb + (size_t)bidx * DDIM);
    float* oq = out + QOFF + (size_t)b * DDIM * HWSZ + hw;
#pragma unroll
    for (int i = 0; i < DDIM / 4; i++) {
        float4 v = __ldg(&er[i]);            // 256KB table, L2-resident
        oq[(size_t)(4 * i + 0) * HWSZ] = v.x;
        oq[(size_t)(4 * i + 1) * HWSZ] = v.y;
        oq[(size_t)(4 * i + 2) * HWSZ] = v.z;
        oq[(size_t)(4 * i + 3) * HWSZ] = v.w;
    }
}

// ---------------------------------------------------------------------------
// Perplexity: exp(-sum p*log(p+1e-10)), p = counts/N. One block, 1024 threads.
// ---------------------------------------------------------------------------
__global__ void vq_perp(float* __restrict__ out) {
    __shared__ float red[KCODES];
    int k = threadIdx.x;
    float p = (float)g_counts[k] * (1.0f / (float)NPTS);
    red[k] = p * logf(p + 1e-10f);
    __syncthreads();
#pragma unroll
    for (int s = KCODES / 2; s > 0; s >>= 1) {
        if (k < s) red[k] += red[k + s];
        __syncthreads();
    }
    if (k == 0) out[POFF] = expf(-red[0]);
}

// ---------------------------------------------------------------------------
extern "C" void kernel_launch(void* const* d_in, const int* in_sizes, int n_in,
                              void* d_out, int out_size) {
    const float* x   = (const float*)d_in[0];   // (32, 64, 64, 64) fp32
    const float* emb = (const float*)d_in[1];   // (1024, 64) fp32
    float* out = (float*)d_out;

    vq_prep<<<1, KCODES>>>(emb);
    vq_main<<<NPTS / 256, 256>>>(x, emb, out);
    vq_perp<<<1, KCODES>>>(out);
}

// round 2
// speedup vs baseline: 1.1741x; 1.1741x over previous
#include <cuda_runtime.h>
#include <cuda_bf16.h>
#include <math.h>
#include <float.h>

// Problem constants
#define NPTS   131072          // 32 * 64 * 64 points
#define DDIM   64
#define KCODES 1024
#define HWSZ   4096            // 64*64
#define QOFF   ((size_t)NPTS)  // quantized segment offset in out
#define QSZ    ((size_t)32*64*4096)
#define POFF   (QOFF + QSZ)    // perplexity scalar offset

typedef unsigned long long ull;

// Scratch (no cudaMalloc allowed)
__device__ int   g_counts[KCODES];
__device__ float g_esq[KCODES];

// ---------------------------------------------------------------------------
// Prep: ||e_k||^2 per code, zero histogram. 8 blocks x 128 threads (MLP!).
// ---------------------------------------------------------------------------
__global__ void vq_prep(const float* __restrict__ emb) {
    int k = blockIdx.x * blockDim.x + threadIdx.x;   // 0..1023
    const float4* row = (const float4*)(emb + (size_t)k * DDIM);
    float s = 0.f;
#pragma unroll
    for (int i = 0; i < DDIM / 4; i++) {
        float4 v = row[i];
        s += v.x * v.x + v.y * v.y + v.z * v.z + v.w * v.w;
    }
    g_esq[k]    = s;
    g_counts[k] = 0;
}

// ---------------------------------------------------------------------------
// Main: 2 points per thread, argmin over 1024 codes.
// Inner loop per code: 16 LDS.128 + 64 FFMA2  (fma-pipe bound, LDS 4x reduced)
// ---------------------------------------------------------------------------
#define CHUNK 128   // codes per smem tile (128*64*4B = 32KB)

#define FFMA2(acc, a, b) \
    asm("fma.rn.f32x2 %0, %1, %2, %0;" : "+l"(acc) : "l"(a), "l"(b))

__device__ __forceinline__ float pairsum(ull a, ull b) {
    float lo0 = __uint_as_float((unsigned)a);
    float hi0 = __uint_as_float((unsigned)(a >> 32));
    float lo1 = __uint_as_float((unsigned)b);
    float hi1 = __uint_as_float((unsigned)(b >> 32));
    return (lo0 + hi0) + (lo1 + hi1);
}

__global__ __launch_bounds__(128)
void vq_main(const float* __restrict__ in, const float* __restrict__ emb,
             float* __restrict__ out) {
    __shared__ float se[CHUNK * DDIM];   // 32 KB
    __shared__ float ssq[CHUNK];

    const int t    = threadIdx.x;
    const int base = blockIdx.x * 256;        // 256 points per block
    const int n0   = base + t;
    const int n1   = base + 128 + t;
    const int b    = base >> 12;              // blocks never straddle images
    const int hw0  = n0 & (HWSZ - 1);
    const int hw1  = n1 & (HWSZ - 1);
    const float* xb0 = in + (size_t)b * DDIM * HWSZ + hw0;
    const float* xb1 = in + (size_t)b * DDIM * HWSZ + hw1;

    // Load both x vectors into packed f32x2 registers (coalesced per warp)
    ull xr0[DDIM / 2], xr1[DDIM / 2];
#pragma unroll
    for (int d = 0; d < DDIM / 2; d++) {
        float a0 = xb0[(size_t)(2 * d)     * HWSZ];
        float c0 = xb0[(size_t)(2 * d + 1) * HWSZ];
        asm("mov.b64 %0, {%1, %2};" : "=l"(xr0[d]) : "f"(a0), "f"(c0));
        float a1 = xb1[(size_t)(2 * d)     * HWSZ];
        float c1 = xb1[(size_t)(2 * d + 1) * HWSZ];
        asm("mov.b64 %0, {%1, %2};" : "=l"(xr1[d]) : "f"(a1), "f"(c1));
    }

    float best0 = FLT_MAX, best1 = FLT_MAX;
    int   bi0 = 0, bi1 = 0;

    for (int c0 = 0; c0 < KCODES; c0 += CHUNK) {
        __syncthreads();
        {   // cooperative tile load: 2048 float4, 16 per thread
            const float4* src = (const float4*)(emb + (size_t)c0 * DDIM);
            float4* dst = (float4*)se;
#pragma unroll
            for (int i = 0; i < (CHUNK * DDIM / 4) / 128; i++)
                dst[t + i * 128] = src[t + i * 128];
            ssq[t] = g_esq[c0 + t];
        }
        __syncthreads();

#pragma unroll 2
        for (int kk = 0; kk < CHUNK; kk++) {
            const ulonglong2* e2 = (const ulonglong2*)(se + kk * DDIM);
            ull a00 = 0ull, a01 = 0ull, a10 = 0ull, a11 = 0ull;
#pragma unroll
            for (int d = 0; d < DDIM / 4; d++) {
                ulonglong2 ev = e2[d];          // LDS.128, warp-broadcast
                FFMA2(a00, xr0[2 * d],     ev.x);
                FFMA2(a01, xr0[2 * d + 1], ev.y);
                FFMA2(a10, xr1[2 * d],     ev.x);
                FFMA2(a11, xr1[2 * d + 1], ev.y);
            }
            float sq = ssq[kk];
            float dist0 = sq - 2.0f * pairsum(a00, a01);
            float dist1 = sq - 2.0f * pairsum(a10, a11);
            if (dist0 < best0) { best0 = dist0; bi0 = c0 + kk; }
            if (dist1 < best1) { best1 = dist1; bi1 = c0 + kk; }
        }
    }

    // ---- epilogue ----
    out[n0] = (float)bi0;
    out[n1] = (float)bi1;
    atomicAdd(&g_counts[bi0], 1);
    atomicAdd(&g_counts[bi1], 1);

    const float4* er0 = (const float4*)(emb + (size_t)bi0 * DDIM);
    const float4* er1 = (const float4*)(emb + (size_t)bi1 * DDIM);
    float* oq0 = out + QOFF + (size_t)b * DDIM * HWSZ + hw0;
    float* oq1 = out + QOFF + (size_t)b * DDIM * HWSZ + hw1;
#pragma unroll
    for (int i = 0; i < DDIM / 4; i++) {
        float4 v0 = __ldg(&er0[i]);             // 256KB table, L2-resident
        float4 v1 = __ldg(&er1[i]);
        oq0[(size_t)(4 * i + 0) * HWSZ] = v0.x;
        oq0[(size_t)(4 * i + 1) * HWSZ] = v0.y;
        oq0[(size_t)(4 * i + 2) * HWSZ] = v0.z;
        oq0[(size_t)(4 * i + 3) * HWSZ] = v0.w;
        oq1[(size_t)(4 * i + 0) * HWSZ] = v1.x;
        oq1[(size_t)(4 * i + 1) * HWSZ] = v1.y;
        oq1[(size_t)(4 * i + 2) * HWSZ] = v1.z;
        oq1[(size_t)(4 * i + 3) * HWSZ] = v1.w;
    }
}

// ---------------------------------------------------------------------------
// Perplexity: exp(-sum p*log(p+1e-10)), p = counts/N. One block, 1024 threads.
// ---------------------------------------------------------------------------
__global__ void vq_perp(float* __restrict__ out) {
    __shared__ float red[32];
    int k = threadIdx.x;
    float p = (float)g_counts[k] * (1.0f / (float)NPTS);
    float v = p * logf(p + 1e-10f);
#pragma unroll
    for (int s = 16; s > 0; s >>= 1)
        v += __shfl_xor_sync(0xffffffffu, v, s);
    if ((k & 31) == 0) red[k >> 5] = v;
    __syncthreads();
    if (k < 32) {
        float w = red[k];
#pragma unroll
        for (int s = 16; s > 0; s >>= 1)
            w += __shfl_xor_sync(0xffffffffu, w, s);
        if (k == 0) out[POFF] = expf(-w);
    }
}

// ---------------------------------------------------------------------------
extern "C" void kernel_launch(void* const* d_in, const int* in_sizes, int n_in,
                              void* d_out, int out_size) {
    const float* x   = (const float*)d_in[0];   // (32, 64, 64, 64) fp32
    const float* emb = (const float*)d_in[1];   // (1024, 64) fp32
    float* out = (float*)d_out;

    vq_prep<<<8, 128>>>(emb);
    vq_main<<<NPTS / 256, 128>>>(x, emb, out);
    vq_perp<<<1, KCODES>>>(out);
}